// round 12
// baseline (speedup 1.0000x reference)
#include <cuda_runtime.h>
#include <cstdint>

// MXFP8 E4M3 quantize->dequantize, 32-element blocks along last axis.
// R11: persistent one-wave grid (608 CTAs = 4/SM, 100% theoretical occ at
// 32 regs) + EXPLICIT software pipeline: next iteration's 256-bit load is
// issued at the top of the loop, before the current chunk is processed and
// stored. R10 failed because asm-volatile loads can't be hoisted across
// asm-volatile stores, killing cross-iteration MLP; here program order
// itself keeps one load always in flight per warp.
//
// Chunk = 8 contiguous floats (one LDG.256); MX block spans 4 lanes
// (shfl.xor 1,2). step % 4 == 0 and the iteration-count boundary is a
// multiple of 4, so 4-lane groups never diverge at the tail.
//
// All scales are exact powers of two built by bit manipulation, so every
// multiply matches the reference's fp32 divide bit-for-bit.

static constexpr int EMAX = 8;           // e4m3
static constexpr float MAX_NORM = 448.0f;

__device__ __forceinline__ void ldg256cs(const float* p, float* v) {
    asm volatile(
        "ld.global.cs.v8.f32 {%0,%1,%2,%3,%4,%5,%6,%7}, [%8];"
        : "=f"(v[0]), "=f"(v[1]), "=f"(v[2]), "=f"(v[3]),
          "=f"(v[4]), "=f"(v[5]), "=f"(v[6]), "=f"(v[7])
        : "l"(p));
}

__device__ __forceinline__ void stg256cs(float* p, const float* v) {
    asm volatile(
        "st.global.cs.v8.f32 [%0], {%1,%2,%3,%4,%5,%6,%7,%8};"
        :: "l"(p),
           "f"(v[0]), "f"(v[1]), "f"(v[2]), "f"(v[3]),
           "f"(v[4]), "f"(v[5]), "f"(v[6]), "f"(v[7])
        : "memory");
}

__device__ __forceinline__ float quant_e4m3(float x, float iscale, float scale) {
    float a = x * iscale;                          // exact (iscale = 2^k)
    uint32_t au = __float_as_uint(a);
    uint32_t ab = au & 0x7fffffffu;                // |a|
    int pe = (int)(ab >> 23) - 127;                // floor(log2|a|), exact for normals
    pe = max(pe, -6);                              // MIN_EXP (denorm region clamp)
    // lshift = 2^(3-pe), inv_lshift = 2^(pe-3); pe in [-6, 8] -> both normal
    float lsh  = __uint_as_float((uint32_t)(130 - pe) << 23);
    float ilsh = __uint_as_float((uint32_t)(124 + pe) << 23);
    // round-half-away-from-zero on magnitude: product is exact, +0.5 rounds once
    float r = floorf(__uint_as_float(ab) * lsh + 0.5f);
    float m = fminf(r * ilsh, MAX_NORM);           // saturate to e4m3 max normal
    float res = m * scale;
    return __uint_as_float(__float_as_uint(res) | (au & 0x80000000u));
}

__global__ void __launch_bounds__(512, 4) mxq_kernel(const float* __restrict__ in,
                                                     float* __restrict__ out,
                                                     int nchunks,   // total 8-float chunks
                                                     int step) {    // grid*block
    int gid = blockIdx.x * blockDim.x + threadIdx.x;

    int idx = gid;
    float a[8];
    if (idx < nchunks)                              // prime the pipeline
        ldg256cs(in + (long)idx * 8, a);

    while (idx < nchunks) {
        int nidx = idx + step;
        float b[8];
        if (nidx < nchunks)                         // prefetch next chunk FIRST
            ldg256cs(in + (long)nidx * 8, b);

        // amax over this thread's 8, reduce across 4-lane group (one MX block)
        float m = fmaxf(fabsf(a[0]), fabsf(a[1]));
        m = fmaxf(m, fmaxf(fabsf(a[2]), fabsf(a[3])));
        m = fmaxf(m, fmaxf(fabsf(a[4]), fabsf(a[5])));
        m = fmaxf(m, fmaxf(fabsf(a[6]), fabsf(a[7])));
        m = fmaxf(m, __shfl_xor_sync(0xffffffffu, m, 1));
        m = fmaxf(m, __shfl_xor_sync(0xffffffffu, m, 2));

        int e = (int)(__float_as_uint(m) >> 23);    // m >= 0, no sign bit
        int se = e - 127 - EMAX;
        se = max(se, -127);
        float scale  = __uint_as_float((uint32_t)(se + 127) << 23);
        float iscale = __uint_as_float((uint32_t)(127 - se) << 23);

#pragma unroll
        for (int i = 0; i < 8; i++) a[i] = quant_e4m3(a[i], iscale, scale);
        stg256cs(out + (long)idx * 8, a);

#pragma unroll
        for (int i = 0; i < 8; i++) a[i] = b[i];    // rotate buffers
        idx = nidx;
    }
}

extern "C" void kernel_launch(void* const* d_in, const int* in_sizes, int n_in,
                              void* d_out, int out_size) {
    const float* in = (const float*)d_in[0];
    float* out = (float*)d_out;
    int n = out_size;                              // 67,108,864 floats
    int nchunks = n / 8;                           // 8,388,608
    int threads = 512;
    int blocks = 608;                              // 4 CTAs/SM x 152 SMs, one wave
    int step = blocks * threads;                   // 311,296 (mult of 4)
    mxq_kernel<<<blocks, threads>>>(in, out, nchunks, step);
}

// round 13
// speedup vs baseline: 1.1231x; 1.1231x over previous
#include <cuda_runtime.h>
#include <cstdint>

// MXFP8 E4M3 quantize->dequantize, 32-element blocks along last axis.
// R12: R8 body (best kernel time: 74.5us, DRAM 82.2%) + .cs evict-first
// cache hints on the 256-bit loads AND stores (R8's asm had silently
// dropped them). 512 MiB streams through L2 exactly once; evict-first
// stops pointless L2 retention/tag churn.
//
// Shape (validated over R2..R11): launch grid 8192x512 (many short CTAs,
// each front-batching its loads), 16 contiguous floats/thread via 2x
// LDG.E.256, forced 32 regs -> 100% theoretical occupancy, MX block spans
// 2 lanes -> single shfl.xor(1) per 32-float block.
//
// All scales are exact powers of two built by bit manipulation, so every
// multiply matches the reference's fp32 divide bit-for-bit.

static constexpr int EMAX = 8;           // e4m3
static constexpr float MAX_NORM = 448.0f;

__device__ __forceinline__ void ldg256cs(const float* p, float* v) {
    asm volatile(
        "ld.global.cs.v8.f32 {%0,%1,%2,%3,%4,%5,%6,%7}, [%8];"
        : "=f"(v[0]), "=f"(v[1]), "=f"(v[2]), "=f"(v[3]),
          "=f"(v[4]), "=f"(v[5]), "=f"(v[6]), "=f"(v[7])
        : "l"(p));
}

__device__ __forceinline__ void stg256cs(float* p, const float* v) {
    asm volatile(
        "st.global.cs.v8.f32 [%0], {%1,%2,%3,%4,%5,%6,%7,%8};"
        :: "l"(p),
           "f"(v[0]), "f"(v[1]), "f"(v[2]), "f"(v[3]),
           "f"(v[4]), "f"(v[5]), "f"(v[6]), "f"(v[7])
        : "memory");
}

__device__ __forceinline__ float quant_e4m3(float x, float iscale, float scale) {
    float a = x * iscale;                          // exact (iscale = 2^k)
    uint32_t au = __float_as_uint(a);
    uint32_t ab = au & 0x7fffffffu;                // |a|
    int pe = (int)(ab >> 23) - 127;                // floor(log2|a|), exact for normals
    pe = max(pe, -6);                              // MIN_EXP (denorm region clamp)
    // lshift = 2^(3-pe), inv_lshift = 2^(pe-3); pe in [-6, 8] -> both normal
    float lsh  = __uint_as_float((uint32_t)(130 - pe) << 23);
    float ilsh = __uint_as_float((uint32_t)(124 + pe) << 23);
    // round-half-away-from-zero on magnitude: product is exact, +0.5 rounds once
    float r = floorf(__uint_as_float(ab) * lsh + 0.5f);
    float m = fminf(r * ilsh, MAX_NORM);           // saturate to e4m3 max normal
    float res = m * scale;
    return __uint_as_float(__float_as_uint(res) | (au & 0x80000000u));
}

__global__ void __launch_bounds__(512, 4) mxq_kernel(const float* __restrict__ in,
                                                     float* __restrict__ out) {
    int gid = blockIdx.x * blockDim.x + threadIdx.x;
    long base = (long)gid * 16;                    // 16 contiguous floats

    // Front-batched 256-bit loads (16 lines in flight per warp)
    float a[8], b[8];
    ldg256cs(in + base, a);
    ldg256cs(in + base + 8, b);

    // amax over this thread's 16, then one shfl across the 2-lane block group
    float m = fmaxf(fabsf(a[0]), fabsf(a[1]));
    m = fmaxf(m, fmaxf(fabsf(a[2]), fabsf(a[3])));
    m = fmaxf(m, fmaxf(fabsf(a[4]), fabsf(a[5])));
    m = fmaxf(m, fmaxf(fabsf(a[6]), fabsf(a[7])));
    m = fmaxf(m, fmaxf(fabsf(b[0]), fabsf(b[1])));
    m = fmaxf(m, fmaxf(fabsf(b[2]), fabsf(b[3])));
    m = fmaxf(m, fmaxf(fabsf(b[4]), fabsf(b[5])));
    m = fmaxf(m, fmaxf(fabsf(b[6]), fabsf(b[7])));
    m = fmaxf(m, __shfl_xor_sync(0xffffffffu, m, 1));

    int e = (int)(__float_as_uint(m) >> 23);       // m >= 0, no sign bit
    int se = e - 127 - EMAX;
    se = max(se, -127);
    float scale  = __uint_as_float((uint32_t)(se + 127) << 23);
    float iscale = __uint_as_float((uint32_t)(127 - se) << 23);

    // Process + store first half (registers retire early), then second half.
#pragma unroll
    for (int i = 0; i < 8; i++) a[i] = quant_e4m3(a[i], iscale, scale);
    stg256cs(out + base, a);
#pragma unroll
    for (int i = 0; i < 8; i++) b[i] = quant_e4m3(b[i], iscale, scale);
    stg256cs(out + base + 8, b);
}

extern "C" void kernel_launch(void* const* d_in, const int* in_sizes, int n_in,
                              void* d_out, int out_size) {
    const float* in = (const float*)d_in[0];
    float* out = (float*)d_out;
    int n = out_size;                              // 67,108,864 floats
    int threads = 512;
    int total_threads = n / 16;                    // 4,194,304
    int blocks = total_threads / threads;          // 8192
    mxq_kernel<<<blocks, threads>>>(in, out);
}